// round 15
// baseline (speedup 1.0000x reference)
#include <cuda_runtime.h>
#include <cuda_bf16.h>

#define HD 128
#define FD 16
#define SD 64
#define NB 8
#define NT 256
#define NCTA 128

typedef unsigned long long u64;

__device__ __align__(16) u64    g_W2d[131072]; // W2 as f-pair u64 words, lane-coalesced (1MB)
__device__ __align__(16) float4 g_W1p[4096];   // permuted W1, lane-coalesced

__device__ __forceinline__ u64 pk2(float lo, float hi) {
    u64 r; asm("mov.b64 %0,{%1,%2};" : "=l"(r) : "f"(lo), "f"(hi)); return r;
}
__device__ __forceinline__ void upk2(u64 v, float& lo, float& hi) {
    asm("mov.b64 {%0,%1},%2;" : "=f"(lo), "=f"(hi) : "l"(v));
}
__device__ __forceinline__ u64 f2fma(u64 a, u64 b, u64 c) {
    u64 d; asm("fma.rn.f32x2 %0,%1,%2,%3;" : "=l"(d) : "l"(a), "l"(b), "l"(c)); return d;
}
__device__ __forceinline__ u64 f2add(u64 a, u64 b) {
    u64 d; asm("add.rn.f32x2 %0,%1,%2;" : "=l"(d) : "l"(a), "l"(b)); return d;
}

// Gather-permute:
// g_W2d[U], U = ((c*8+kk)*2 + (fp>>1))*512 + 2*t + (fp&1)
//   = ( W2[r0][k], W2[r0+1][k] ),  r0 = (t>>1)*16 + (t&1)*8 + 2*fp,  k = c*8+kk
// g_W1p[o2], o2 = jc*128 + kx  ->  W1[kx][jc*4 .. +3]
__global__ void perm_kernel(const float* __restrict__ W1, const float* __restrict__ W2) {
    int o = blockIdx.x * 256 + threadIdx.x;
    if (o < 131072) {
        int t = o & 255, fp = (o >> 8) & 3, kk = (o >> 10) & 7, c = o >> 13;
        int r0 = (t >> 1) * 16 + (t & 1) * 8 + 2 * fp;
        int k  = c * 8 + kk;
        u64 U = (u64)((((c * 8 + kk) * 2 + (fp >> 1)) * 512) + 2 * t + (fp & 1));
        g_W2d[U] = pk2(W2[r0 * HD + k], W2[(r0 + 1) * HD + k]);
    } else {
        int o2 = o - 131072;
        if (o2 < 4096) {
            int jc = o2 >> 7, kx = o2 & 127;
            g_W1p[o2] = ((const float4*)W1)[kx * 32 + jc];
        }
    }
}

__global__ void __launch_bounds__(NT, 1) cde_kernel(
    const float* __restrict__ x,   const float* __restrict__ W1,
    const float* __restrict__ b1v, const float* __restrict__ W2,
    const float* __restrict__ b2v, const float* __restrict__ Wi,
    const float* __restrict__ biv, float* __restrict__ out)
{
    __shared__ float sh_h [NB][HD];
    __shared__ __align__(16) float sh_hsT[HD][NB];     // hs transposed: j-major
    __shared__ __align__(16) float sh_zD[HD][NB][2];   // z duplicated pairs (z,z)
    __shared__ float sh_kk[4][NB][HD];
    __shared__ __align__(16) u64 sh_dxf4[4][NB][8];    // dX f-pairs: [e][b][fh*4+fp]
    __shared__ float sh_b1[HD];

    const int t   = threadIdx.x;
    const int gb0 = blockIdx.x * NB;

    if (t < HD) sh_b1[t] = b1v[t];

    // b2 registers: thread owns rows (t>>1)*16 + (t&1)*8 .. +7
    float b2r[8];
    {
        int j0 = (t >> 1) * 16 + (t & 1) * 8;
        #pragma unroll
        for (int f = 0; f < 8; f++) b2r[f] = b2v[j0 + f];
    }

    // h0 = x[:,0] @ Wi^T + bi
    for (int it = t; it < NB * HD; it += NT) {
        int b = it >> 7, j = it & (HD - 1);
        const float* xr = x + (size_t)(gb0 + b) * (SD * FD);
        float acc = biv[j];
        #pragma unroll
        for (int f = 0; f < FD; f++) acc = fmaf(xr[f], Wi[j * FD + f], acc);
        sh_h[b][j] = acc;
    }
    __syncthreads();

    const float step = 1.0f / 63.0f;
    float r_segp = 0.0f;
    const int hb = t >> 4;   // hermite mapping (t < 128): batch 0..7
    const int hf = t & 15;   // feature

    #pragma unroll 1
    for (int i = 0; i < SD - 1; i++) {
        const float tA  = i * step;
        const float tB  = (i == SD - 2) ? 1.0f : (i + 1) * step;
        const float dti = tB - tA;

        // Hermite coeffs + all 4 evals' dX (f-paired) for this interval
        if (t < NB * FD) {
            const float* xr = x + ((size_t)(gb0 + hb) * SD + i) * FD + hf;
            float p0 = xr[0], p1 = xr[FD];
            float seg = (p1 - p0) / dti;
            float m0  = (i == 0) ? seg : r_segp;
            r_segp = seg;
            float cc = (3.0f * seg - (2.0f * m0 + seg)) / dti;
            float dd = (-2.0f * seg + (m0 + seg)) / (dti * dti);
            #pragma unroll
            for (int e = 0; e < 4; e++) {
                float fe = (e == 0) ? 0.0f
                         : (e == 1) ? dti * (1.0f / 3.0f)
                         : (e == 2) ? dti * (2.0f / 3.0f)
                         : dti;
                float dx = (e == 0) ? m0
                                    : fmaf(fmaf(3.0f * dd, fe, 2.0f * cc), fe, m0);
                float dxn = __shfl_down_sync(0xFFFFFFFFu, dx, 1);   // (f, f+1) pair
                if ((hf & 1) == 0) sh_dxf4[e][hb][hf >> 1] = pk2(dx, dxn);
            }
        }

        #pragma unroll 1
        for (int e = 0; e < 4; e++) {
            // stage RK input hs (transposed: j-major)
            for (int it = t; it < NB * HD; it += NT) {
                int b = it >> 7, j = it & (HD - 1);
                float hv = sh_h[b][j];
                if (e == 1)      hv = fmaf(dti * (1.0f / 3.0f), sh_kk[0][b][j], hv);
                else if (e == 2) hv = fmaf(dti, sh_kk[1][b][j] - sh_kk[0][b][j] * (1.0f / 3.0f), hv);
                else if (e == 3) hv = fmaf(dti, sh_kk[0][b][j] - sh_kk[1][b][j] + sh_kk[2][b][j], hv);
                sh_hsT[j][b] = hv;
            }
            __syncthreads();

            // ---- phase A: z = tanh(hs @ W1^T + b1), f32x2 over batch-pairs ----
            {
                int kx = t & (HD - 1), half = t >> 7, b0v = half * 4;
                u64 bp = pk2(sh_b1[kx], sh_b1[kx]);
                u64 a01 = bp, a23 = bp;
                #pragma unroll
                for (int jc = 0; jc < HD / 4; jc++) {
                    float4 w = __ldg(&g_W1p[jc * HD + kx]);
                    #define ASTEP(wv, jj) { \
                        ulonglong2 hp = *(const ulonglong2*)&sh_hsT[jc * 4 + jj][b0v]; \
                        u64 wp = pk2(wv, wv); \
                        a01 = f2fma(wp, hp.x, a01); \
                        a23 = f2fma(wp, hp.y, a23); }
                    ASTEP(w.x, 0) ASTEP(w.y, 1) ASTEP(w.z, 2) ASTEP(w.w, 3)
                    #undef ASTEP
                }
                float v0, v1, v2, v3;
                upk2(a01, v0, v1); upk2(a23, v2, v3);
                float z0 = tanhf(v0), z1 = tanhf(v1), z2 = tanhf(v2), z3 = tanhf(v3);
                float4 w0; w0.x = z0; w0.y = z0; w0.z = z1; w0.w = z1;
                float4 w1; w1.x = z2; w1.y = z2; w1.z = z3; w1.w = z3;
                *(float4*)&sh_zD[kx][b0v][0]     = w0;   // duplicated pairs
                *(float4*)&sh_zD[kx][b0v + 2][0] = w1;
            }
            __syncthreads();

            // ---- phase B: W2 GEMV with f-pair lanes, zero in-loop packing ----
            {
                const ulonglong2* W2d2 = (const ulonglong2*)g_W2d;
                u64 acc[4][8];                        // [fp][b], lanes (even f, odd f)
                #pragma unroll
                for (int fp = 0; fp < 4; fp++)
                    #pragma unroll
                    for (int b = 0; b < 8; b++) acc[fp][b] = 0;

                // preload chunk 0 (16 LDG.128)
                ulonglong2 wbuf[16];
                #pragma unroll
                for (int u = 0; u < 16; u++) wbuf[u] = __ldcs(&W2d2[u * 256 + t]);

                #pragma unroll 1
                for (int c = 0; c < 16; c++) {
                    const int cn = (c + 1 < 16) ? c + 1 : 15;
                    #pragma unroll
                    for (int kk = 0; kk < 8; kk++) {
                        // z duplicated pairs for this k: 4 broadcast LDS.128
                        ulonglong2 z01 = *(const ulonglong2*)&sh_zD[c * 8 + kk][0][0];
                        ulonglong2 z23 = *(const ulonglong2*)&sh_zD[c * 8 + kk][2][0];
                        ulonglong2 z45 = *(const ulonglong2*)&sh_zD[c * 8 + kk][4][0];
                        ulonglong2 z67 = *(const ulonglong2*)&sh_zD[c * 8 + kk][6][0];
                        ulonglong2 wA = wbuf[kk * 2];       // fp0, fp1
                        ulonglong2 wB = wbuf[kk * 2 + 1];   // fp2, fp3
                        wbuf[kk * 2]     = __ldcs(&W2d2[cn * 4096 + (kk * 2 + 0) * 256 + t]);
                        wbuf[kk * 2 + 1] = __ldcs(&W2d2[cn * 4096 + (kk * 2 + 1) * 256 + t]);
                        #define BSTEP(zd, b) { \
                            acc[0][b] = f2fma(wA.x, zd, acc[0][b]); \
                            acc[1][b] = f2fma(wA.y, zd, acc[1][b]); \
                            acc[2][b] = f2fma(wB.x, zd, acc[2][b]); \
                            acc[3][b] = f2fma(wB.y, zd, acc[3][b]); }
                        BSTEP(z01.x, 0) BSTEP(z01.y, 1) BSTEP(z23.x, 2) BSTEP(z23.y, 3)
                        BSTEP(z45.x, 4) BSTEP(z45.y, 5) BSTEP(z67.x, 6) BSTEP(z67.y, 7)
                        #undef BSTEP
                    }
                }

                // fold b2 and dX (f-pair lanes), then horizontal add
                const int fh = t & 1;
                u64 totp[8];
                #pragma unroll
                for (int b = 0; b < 8; b++) totp[b] = 0;
                #pragma unroll
                for (int fp = 0; fp < 4; fp++) {
                    u64 b2p = pk2(b2r[2 * fp], b2r[2 * fp + 1]);
                    #pragma unroll
                    for (int b = 0; b < 8; b++) {
                        u64 s  = f2add(acc[fp][b], b2p);
                        u64 dq = sh_dxf4[e][b][fh * 4 + fp];
                        totp[b] = f2fma(dq, s, totp[b]);
                    }
                }

                float tv[8];
                #pragma unroll
                for (int b = 0; b < 8; b++) {
                    float lo, hi; upk2(totp[b], lo, hi);
                    tv[b] = lo + hi;
                }
                const int j = t >> 1;
                #pragma unroll
                for (int b = 0; b < 8; b++)
                    tv[b] += __shfl_xor_sync(0xFFFFFFFFu, tv[b], 1);
                if (fh == 0) {
                    #pragma unroll
                    for (int b = 0; b < 8; b++) sh_kk[e][b][j] = tv[b];
                }
            }
            __syncthreads();
        }

        // h += dt*(k1 + 3(k2+k3) + k4)/8
        for (int it = t; it < NB * HD; it += NT) {
            int b = it >> 7, j = it & (HD - 1);
            float k1 = sh_kk[0][b][j], k2 = sh_kk[1][b][j];
            float k3 = sh_kk[2][b][j], k4 = sh_kk[3][b][j];
            sh_h[b][j] = fmaf(dti * 0.125f, k1 + 3.0f * (k2 + k3) + k4, sh_h[b][j]);
        }
        __syncthreads();
    }

    for (int it = t; it < NB * HD; it += NT) {
        int b = it >> 7, j = it & (HD - 1);
        out[(size_t)(gb0 + b) * HD + j] = sh_h[b][j];
    }
}

extern "C" void kernel_launch(void* const* d_in, const int* in_sizes, int n_in,
                              void* d_out, int out_size) {
    const float* x   = (const float*)d_in[0];
    const float* W1  = (const float*)d_in[1];
    const float* b1  = (const float*)d_in[2];
    const float* W2  = (const float*)d_in[3];
    const float* b2  = (const float*)d_in[4];
    const float* Wi  = (const float*)d_in[5];
    const float* bi  = (const float*)d_in[6];
    float* out = (float*)d_out;
    perm_kernel<<<528, 256>>>(W1, W2);
    cde_kernel<<<NCTA, NT>>>(x, W1, b1, W2, b2, Wi, bi, out);
}

// round 16
// speedup vs baseline: 1.0429x; 1.0429x over previous
#include <cuda_runtime.h>
#include <cuda_bf16.h>

#define HD 128
#define FD 16
#define SD 64
#define NB 8
#define NT 512
#define NCTA 128

typedef unsigned long long u64;

__device__ __align__(16) float4 g_W2p[65536]; // permuted W2, lane-coalesced (512-thr layout)
__device__ __align__(16) float4 g_W1p[4096];  // permuted W1, lane-coalesced

__device__ __forceinline__ u64 pk2(float lo, float hi) {
    u64 r; asm("mov.b64 %0,{%1,%2};" : "=l"(r) : "f"(lo), "f"(hi)); return r;
}
__device__ __forceinline__ void upk2(u64 v, float& lo, float& hi) {
    asm("mov.b64 {%0,%1},%2;" : "=f"(lo), "=f"(hi) : "l"(v));
}
__device__ __forceinline__ u64 f2fma(u64 a, u64 b, u64 c) {
    u64 d; asm("fma.rn.f32x2 %0,%1,%2,%3;" : "=l"(d) : "l"(a), "l"(b), "l"(c)); return d;
}
__device__ __forceinline__ u64 f2add(u64 a, u64 b) {
    u64 d; asm("add.rn.f32x2 %0,%1,%2;" : "=l"(d) : "l"(a), "l"(b)); return d;
}

// W2p[o], o = ((c*4+fi)*2+h)*512 + t  ->  W2[row(t,fi)][c*8+h*4 .. +3]
//   row(t,fi) = (t>>2)*16 + (t&3)*4 + fi
// W1p[o2], o2 = jc*128 + kx           ->  W1[kx][jc*4 .. +3]
__global__ void perm_kernel(const float* __restrict__ W1, const float* __restrict__ W2) {
    int o = blockIdx.x * 256 + threadIdx.x;
    if (o < 65536) {
        int t = o & 511, h = (o >> 9) & 1, fi = (o >> 10) & 3, c = o >> 12;
        int r = (t >> 2) * 16 + (t & 3) * 4 + fi;
        g_W2p[o] = ((const float4*)W2)[r * 32 + c * 2 + h];
    } else {
        int o2 = o - 65536;
        int jc = o2 >> 7, kx = o2 & 127;
        g_W1p[o2] = ((const float4*)W1)[kx * 32 + jc];
    }
}

__global__ void __launch_bounds__(NT, 1) cde_kernel(
    const float* __restrict__ x,   const float* __restrict__ W1,
    const float* __restrict__ b1v, const float* __restrict__ W2,
    const float* __restrict__ b2v, const float* __restrict__ Wi,
    const float* __restrict__ biv, float* __restrict__ out)
{
    __shared__ float sh_h [NB][HD];
    __shared__ __align__(16) float sh_hsT[HD][NB];     // hs transposed: j-major
    __shared__ __align__(16) float sh_zT[HD][NB];      // z transposed: k-major
    __shared__ float sh_kk[4][NB][HD];
    __shared__ __align__(16) u64 sh_dxp4[4][FD][NB/2]; // dX per eval, packed batch-pairs
    __shared__ float sh_b1[HD];

    const int t   = threadIdx.x;
    const int gb0 = blockIdx.x * NB;

    if (t < HD) sh_b1[t] = b1v[t];

    // b2 registers: thread owns rows (t>>2)*16 + (t&3)*4 .. +3
    float b2r[4];
    {
        int j0 = (t >> 2) * 16 + (t & 3) * 4;
        #pragma unroll
        for (int fi = 0; fi < 4; fi++) b2r[fi] = b2v[j0 + fi];
    }

    // h0 = x[:,0] @ Wi^T + bi
    for (int it = t; it < NB * HD; it += NT) {
        int b = it >> 7, j = it & (HD - 1);
        const float* xr = x + (size_t)(gb0 + b) * (SD * FD);
        float acc = biv[j];
        #pragma unroll
        for (int f = 0; f < FD; f++) acc = fmaf(xr[f], Wi[j * FD + f], acc);
        sh_h[b][j] = acc;
    }
    __syncthreads();

    const float step = 1.0f / 63.0f;
    float r_segp = 0.0f;
    const int hb = t >> 4;   // hermite mapping (t < 128): batch 0..7
    const int hf = t & 15;   // feature

    #pragma unroll 1
    for (int i = 0; i < SD - 1; i++) {
        const float tA  = i * step;
        const float tB  = (i == SD - 2) ? 1.0f : (i + 1) * step;
        const float dti = tB - tA;

        // Hermite coeffs + all 4 evals' dX (threads 0..127)
        if (t < NB * FD) {
            const float* xr = x + ((size_t)(gb0 + hb) * SD + i) * FD + hf;
            float p0 = xr[0], p1 = xr[FD];
            float seg = (p1 - p0) / dti;
            float m0  = (i == 0) ? seg : r_segp;
            r_segp = seg;
            float cc = (3.0f * seg - (2.0f * m0 + seg)) / dti;
            float dd = (-2.0f * seg + (m0 + seg)) / (dti * dti);
            #pragma unroll
            for (int e = 0; e < 4; e++) {
                float fe = (e == 0) ? 0.0f
                         : (e == 1) ? dti * (1.0f / 3.0f)
                         : (e == 2) ? dti * (2.0f / 3.0f)
                         : dti;
                float dx = (e == 0) ? m0
                                    : fmaf(fmaf(3.0f * dd, fe, 2.0f * cc), fe, m0);
                float dxh = __shfl_down_sync(0xFFFFFFFFu, dx, 16);
                if ((t & 31) < 16) sh_dxp4[e][hf][t >> 5] = pk2(dx, dxh);
            }
        }

        #pragma unroll 1
        for (int e = 0; e < 4; e++) {
            // stage RK input hs (transposed: j-major)
            for (int it = t; it < NB * HD; it += NT) {
                int b = it >> 7, j = it & (HD - 1);
                float hv = sh_h[b][j];
                if (e == 1)      hv = fmaf(dti * (1.0f / 3.0f), sh_kk[0][b][j], hv);
                else if (e == 2) hv = fmaf(dti, sh_kk[1][b][j] - sh_kk[0][b][j] * (1.0f / 3.0f), hv);
                else if (e == 3) hv = fmaf(dti, sh_kk[0][b][j] - sh_kk[1][b][j] + sh_kk[2][b][j], hv);
                sh_hsT[j][b] = hv;
            }
            __syncthreads();

            // ---- phase A: z = tanh(hs @ W1^T + b1), f32x2, thread=(kx, 2-batch grp) ----
            {
                int kx = t & (HD - 1), grp = t >> 7, b0v = grp * 2;
                u64 a01 = pk2(sh_b1[kx], sh_b1[kx]);
                #pragma unroll
                for (int jc = 0; jc < HD / 4; jc++) {
                    float4 w = __ldg(&g_W1p[jc * HD + kx]);
                    #define ASTEP(wv, jj) { \
                        u64 hp = *(const u64*)&sh_hsT[jc * 4 + jj][b0v]; \
                        a01 = f2fma(pk2(wv, wv), hp, a01); }
                    ASTEP(w.x, 0) ASTEP(w.y, 1) ASTEP(w.z, 2) ASTEP(w.w, 3)
                    #undef ASTEP
                }
                float v0, v1;
                upk2(a01, v0, v1);
                float2 zr; zr.x = tanhf(v0); zr.y = tanhf(v1);
                *(float2*)&sh_zT[kx][b0v] = zr;
            }
            __syncthreads();

            // ---- phase B: pipelined W2 GEMV, thread=(j, fq) with 4 f each ----
            {
                u64 acc[4][4];
                #pragma unroll
                for (int fi = 0; fi < 4; fi++) {
                    acc[fi][0] = 0; acc[fi][1] = 0; acc[fi][2] = 0; acc[fi][3] = 0;
                }
                float4 bufA[4], bufB[4];
                #pragma unroll
                for (int fi = 0; fi < 4; fi++) bufA[fi] = __ldcs(&g_W2p[(fi * 2 + 0) * 512 + t]);
                #pragma unroll
                for (int fi = 0; fi < 4; fi++) bufB[fi] = __ldcs(&g_W2p[(fi * 2 + 1) * 512 + t]);

                #pragma unroll 1
                for (int c = 0; c < 16; c++) {
                    const int cn = (c + 1 < 16) ? c + 1 : 15;

                    #define WSTEP(wv, fi) { u64 wp = pk2(wv, wv); \
                        acc[fi][0] = f2fma(wp, za.x, acc[fi][0]); \
                        acc[fi][1] = f2fma(wp, za.y, acc[fi][1]); \
                        acc[fi][2] = f2fma(wp, zb.x, acc[fi][2]); \
                        acc[fi][3] = f2fma(wp, zb.y, acc[fi][3]); }
                    #define KSTEP(w0, w1, w2, w3, kidx) { \
                        ulonglong2 za = *(const ulonglong2*)&sh_zT[(kidx)][0]; \
                        ulonglong2 zb = *(const ulonglong2*)&sh_zT[(kidx)][4]; \
                        WSTEP(w0, 0) WSTEP(w1, 1) WSTEP(w2, 2) WSTEP(w3, 3) }

                    KSTEP(bufA[0].x, bufA[1].x, bufA[2].x, bufA[3].x, c * 8 + 0)
                    KSTEP(bufA[0].y, bufA[1].y, bufA[2].y, bufA[3].y, c * 8 + 1)
                    KSTEP(bufA[0].z, bufA[1].z, bufA[2].z, bufA[3].z, c * 8 + 2)
                    KSTEP(bufA[0].w, bufA[1].w, bufA[2].w, bufA[3].w, c * 8 + 3)
                    #pragma unroll
                    for (int fi = 0; fi < 4; fi++)
                        bufA[fi] = __ldcs(&g_W2p[((cn * 4 + fi) * 2 + 0) * 512 + t]);

                    KSTEP(bufB[0].x, bufB[1].x, bufB[2].x, bufB[3].x, c * 8 + 4)
                    KSTEP(bufB[0].y, bufB[1].y, bufB[2].y, bufB[3].y, c * 8 + 5)
                    KSTEP(bufB[0].z, bufB[1].z, bufB[2].z, bufB[3].z, c * 8 + 6)
                    KSTEP(bufB[0].w, bufB[1].w, bufB[2].w, bufB[3].w, c * 8 + 7)
                    #pragma unroll
                    for (int fi = 0; fi < 4; fi++)
                        bufB[fi] = __ldcs(&g_W2p[((cn * 4 + fi) * 2 + 1) * 512 + t]);

                    #undef KSTEP
                    #undef WSTEP
                }

                // fold b2 + dX, then reduce over the 4 f-lanes
                const int j = t >> 2, fq = t & 3;
                u64 totp[4];
                totp[0] = 0; totp[1] = 0; totp[2] = 0; totp[3] = 0;
                #pragma unroll
                for (int fi = 0; fi < 4; fi++) {
                    int f = fq * 4 + fi;
                    u64 b2p = pk2(b2r[fi], b2r[fi]);
                    #pragma unroll
                    for (int p = 0; p < 4; p++) {
                        u64 s = f2add(acc[fi][p], b2p);
                        totp[p] = f2fma(sh_dxp4[e][f][p], s, totp[p]);
                    }
                }
                float tv[8];
                upk2(totp[0], tv[0], tv[1]); upk2(totp[1], tv[2], tv[3]);
                upk2(totp[2], tv[4], tv[5]); upk2(totp[3], tv[6], tv[7]);
                #pragma unroll
                for (int b = 0; b < 8; b++) {
                    tv[b] += __shfl_xor_sync(0xFFFFFFFFu, tv[b], 1);
                    tv[b] += __shfl_xor_sync(0xFFFFFFFFu, tv[b], 2);
                }
                if (fq == 0) {
                    #pragma unroll
                    for (int b = 0; b < 8; b++) sh_kk[e][b][j] = tv[b];
                }
            }
            __syncthreads();
        }

        // h += dt*(k1 + 3(k2+k3) + k4)/8
        for (int it = t; it < NB * HD; it += NT) {
            int b = it >> 7, j = it & (HD - 1);
            float k1 = sh_kk[0][b][j], k2 = sh_kk[1][b][j];
            float k3 = sh_kk[2][b][j], k4 = sh_kk[3][b][j];
            sh_h[b][j] = fmaf(dti * 0.125f, k1 + 3.0f * (k2 + k3) + k4, sh_h[b][j]);
        }
        __syncthreads();
    }

    for (int it = t; it < NB * HD; it += NT) {
        int b = it >> 7, j = it & (HD - 1);
        out[(size_t)(gb0 + b) * HD + j] = sh_h[b][j];
    }
}

extern "C" void kernel_launch(void* const* d_in, const int* in_sizes, int n_in,
                              void* d_out, int out_size) {
    const float* x   = (const float*)d_in[0];
    const float* W1  = (const float*)d_in[1];
    const float* b1  = (const float*)d_in[2];
    const float* W2  = (const float*)d_in[3];
    const float* b2  = (const float*)d_in[4];
    const float* Wi  = (const float*)d_in[5];
    const float* bi  = (const float*)d_in[6];
    float* out = (float*)d_out;
    perm_kernel<<<272, 256>>>(W1, W2);
    cde_kernel<<<NCTA, NT>>>(x, W1, b1, W2, b2, Wi, bi, out);
}

// round 17
// speedup vs baseline: 1.1547x; 1.1072x over previous
#include <cuda_runtime.h>
#include <cuda_bf16.h>

#define HD 128
#define FD 16
#define SD 64
#define NB 8
#define NT 256
#define NCTA 128

typedef unsigned long long u64;

__device__ __align__(16) float4 g_W2p[65536]; // permuted W2, lane-coalesced
__device__ __align__(16) float4 g_W1p[4096];  // permuted W1, lane-coalesced

__device__ __forceinline__ u64 pk2(float lo, float hi) {
    u64 r; asm("mov.b64 %0,{%1,%2};" : "=l"(r) : "f"(lo), "f"(hi)); return r;
}
__device__ __forceinline__ void upk2(u64 v, float& lo, float& hi) {
    asm("mov.b64 {%0,%1},%2;" : "=f"(lo), "=f"(hi) : "l"(v));
}
__device__ __forceinline__ u64 f2fma(u64 a, u64 b, u64 c) {
    u64 d; asm("fma.rn.f32x2 %0,%1,%2,%3;" : "=l"(d) : "l"(a), "l"(b), "l"(c)); return d;
}
__device__ __forceinline__ u64 f2add(u64 a, u64 b) {
    u64 d; asm("add.rn.f32x2 %0,%1,%2;" : "=l"(d) : "l"(a), "l"(b)); return d;
}

// One-shot gather-permute (R10 layout).
// W2p[o], o = ((c*8+f)*2+h)*256 + t  ->  W2[row(t,f)][c*8+h*4 .. +3]
//   row(t,f) = (t>>1)*16 + (t&1)*8 + f
// W1p[o2], o2 = jc*128 + kx          ->  W1[kx][jc*4 .. +3]
__global__ void perm_kernel(const float* __restrict__ W1, const float* __restrict__ W2) {
    int o = blockIdx.x * 256 + threadIdx.x;
    if (o < 65536) {
        int t = o & 255, h = (o >> 8) & 1, f = (o >> 9) & 7, c = o >> 12;
        int r = (t >> 1) * 16 + (t & 1) * 8 + f;
        g_W2p[o] = ((const float4*)W2)[r * 32 + c * 2 + h];
    } else {
        int o2 = o - 65536;
        int jc = o2 >> 7, kx = o2 & 127;
        g_W1p[o2] = ((const float4*)W1)[kx * 32 + jc];
    }
}

__global__ void __launch_bounds__(NT, 1) cde_kernel(
    const float* __restrict__ x,   const float* __restrict__ W1,
    const float* __restrict__ b1v, const float* __restrict__ W2,
    const float* __restrict__ b2v, const float* __restrict__ Wi,
    const float* __restrict__ biv, float* __restrict__ out)
{
    __shared__ __align__(16) float sh_hsT[HD][NB];     // hs transposed: j-major
    __shared__ __align__(16) float sh_zT[HD][NB];      // z transposed: k-major
    __shared__ __align__(16) u64 sh_dxp4[4][FD][NB/2]; // dX per eval, packed batch-pairs
    __shared__ float sh_b1[HD];

    const int t   = threadIdx.x;
    const int gb0 = blockIdx.x * NB;
    const int j   = t >> 1;      // output row owned by this thread
    const int fh  = t & 1;       // f-half

    if (t < HD) sh_b1[t] = b1v[t];

    // b2 registers: thread owns rows j*16 + fh*8 .. +7
    float b2r[8];
    #pragma unroll
    for (int f = 0; f < 8; f++) b2r[f] = b2v[j * FD + fh * 8 + f];

    // Register-resident RK state: this thread's 4 batches are b = fh*4 + i
    float hreg[4], k1r[4], k2r[4], k3r[4];

    // h0 = x[:,0] @ Wi^T + bi   (compute my 4 batches, stage hsT for e0)
    #pragma unroll
    for (int bi_ = 0; bi_ < 4; bi_++) {
        int b = fh * 4 + bi_;
        const float* xr = x + (size_t)(gb0 + b) * (SD * FD);
        float acc = biv[j];
        #pragma unroll
        for (int f = 0; f < FD; f++) acc = fmaf(xr[f], Wi[j * FD + f], acc);
        hreg[bi_] = acc;
        sh_hsT[j][b] = acc;
    }
    __syncthreads();

    const float step = 1.0f / 63.0f;
    float r_segp = 0.0f;
    const int hb = t >> 4;   // hermite mapping (t < 128): batch 0..7
    const int hf = t & 15;   // feature

    #pragma unroll 1
    for (int i = 0; i < SD - 1; i++) {
        const float tA  = i * step;
        const float tB  = (i == SD - 2) ? 1.0f : (i + 1) * step;
        const float dti = tB - tA;

        // Hermite coeffs + all 4 evals' dX (threads 0..127)
        if (t < NB * FD) {
            const float* xr = x + ((size_t)(gb0 + hb) * SD + i) * FD + hf;
            float p0 = xr[0], p1 = xr[FD];
            float seg = (p1 - p0) / dti;
            float m0  = (i == 0) ? seg : r_segp;
            r_segp = seg;
            float cc = (3.0f * seg - (2.0f * m0 + seg)) / dti;
            float dd = (-2.0f * seg + (m0 + seg)) / (dti * dti);
            #pragma unroll
            for (int e = 0; e < 4; e++) {
                float fe = (e == 0) ? 0.0f
                         : (e == 1) ? dti * (1.0f / 3.0f)
                         : (e == 2) ? dti * (2.0f / 3.0f)
                         : dti;
                float dx = (e == 0) ? m0
                                    : fmaf(fmaf(3.0f * dd, fe, 2.0f * cc), fe, m0);
                float dxh = __shfl_down_sync(0xFFFFFFFFu, dx, 16);
                if ((t & 31) < 16) sh_dxp4[e][hf][t >> 5] = pk2(dx, dxh);
            }
        }

        #pragma unroll 1
        for (int e = 0; e < 4; e++) {
            // ---- phase A: z = tanh(hs @ W1^T + b1), f32x2 over batch-pairs ----
            {
                int kx = t & (HD - 1), half = t >> 7, b0v = half * 4;
                u64 bp = pk2(sh_b1[kx], sh_b1[kx]);
                u64 a01 = bp, a23 = bp;
                #pragma unroll
                for (int jc = 0; jc < HD / 4; jc++) {
                    float4 w = __ldg(&g_W1p[jc * HD + kx]);
                    #define ASTEP(wv, jj) { \
                        ulonglong2 hp = *(const ulonglong2*)&sh_hsT[jc * 4 + jj][b0v]; \
                        u64 wp = pk2(wv, wv); \
                        a01 = f2fma(wp, hp.x, a01); \
                        a23 = f2fma(wp, hp.y, a23); }
                    ASTEP(w.x, 0) ASTEP(w.y, 1) ASTEP(w.z, 2) ASTEP(w.w, 3)
                    #undef ASTEP
                }
                float v0, v1, v2, v3;
                upk2(a01, v0, v1); upk2(a23, v2, v3);
                float4 zr;
                zr.x = tanhf(v0); zr.y = tanhf(v1); zr.z = tanhf(v2); zr.w = tanhf(v3);
                *(float4*)&sh_zT[kx][b0v] = zr;
            }
            __syncthreads();

            // ---- phase B: pipelined W2 GEMV + in-register RK state update ----
            {
                u64 acc[8][4];
                #pragma unroll
                for (int f = 0; f < 8; f++) {
                    acc[f][0] = 0; acc[f][1] = 0; acc[f][2] = 0; acc[f][3] = 0;
                }
                float4 bufA[8], bufB[8];
                #pragma unroll
                for (int f = 0; f < 8; f++) bufA[f] = __ldcs(&g_W2p[(f * 2 + 0) * 256 + t]);
                #pragma unroll
                for (int f = 0; f < 8; f++) bufB[f] = __ldcs(&g_W2p[(f * 2 + 1) * 256 + t]);

                #pragma unroll 1
                for (int c = 0; c < 16; c++) {
                    const int cn = (c + 1 < 16) ? c + 1 : 15;

                    u64 zp[4][4];
                    #pragma unroll
                    for (int kk = 0; kk < 4; kk++) {
                        ulonglong2 za = *(const ulonglong2*)&sh_zT[c * 8 + kk][0];
                        ulonglong2 zb = *(const ulonglong2*)&sh_zT[c * 8 + kk][4];
                        zp[kk][0] = za.x; zp[kk][1] = za.y;
                        zp[kk][2] = zb.x; zp[kk][3] = zb.y;
                    }
                    #pragma unroll
                    for (int f = 0; f < 8; f++) {
                        float4 w = bufA[f];
                        bufA[f] = __ldcs(&g_W2p[((cn * 8 + f) * 2 + 0) * 256 + t]);
                        #define STEPP(wv, kk) { u64 wp = pk2(wv, wv); \
                            acc[f][0] = f2fma(wp, zp[kk][0], acc[f][0]); \
                            acc[f][1] = f2fma(wp, zp[kk][1], acc[f][1]); \
                            acc[f][2] = f2fma(wp, zp[kk][2], acc[f][2]); \
                            acc[f][3] = f2fma(wp, zp[kk][3], acc[f][3]); }
                        STEPP(w.x, 0) STEPP(w.y, 1) STEPP(w.z, 2) STEPP(w.w, 3)
                    }
                    #pragma unroll
                    for (int kk = 0; kk < 4; kk++) {
                        ulonglong2 za = *(const ulonglong2*)&sh_zT[c * 8 + 4 + kk][0];
                        ulonglong2 zb = *(const ulonglong2*)&sh_zT[c * 8 + 4 + kk][4];
                        zp[kk][0] = za.x; zp[kk][1] = za.y;
                        zp[kk][2] = zb.x; zp[kk][3] = zb.y;
                    }
                    #pragma unroll
                    for (int f = 0; f < 8; f++) {
                        float4 w = bufB[f];
                        bufB[f] = __ldcs(&g_W2p[((cn * 8 + f) * 2 + 1) * 256 + t]);
                        STEPP(w.x, 0) STEPP(w.y, 1) STEPP(w.z, 2) STEPP(w.w, 3)
                        #undef STEPP
                    }
                }

                // fold b2 and dX
                u64 tot0 = 0, tot1 = 0, tot2 = 0, tot3 = 0;
                #pragma unroll
                for (int f = 0; f < 8; f++) {
                    u64 bp = pk2(b2r[f], b2r[f]);
                    u64 s0 = f2add(acc[f][0], bp);
                    u64 s1 = f2add(acc[f][1], bp);
                    u64 s2 = f2add(acc[f][2], bp);
                    u64 s3 = f2add(acc[f][3], bp);
                    ulonglong2 qa = *(const ulonglong2*)&sh_dxp4[e][fh * 8 + f][0];
                    ulonglong2 qb = *(const ulonglong2*)&sh_dxp4[e][fh * 8 + f][2];
                    tot0 = f2fma(qa.x, s0, tot0); tot1 = f2fma(qa.y, s1, tot1);
                    tot2 = f2fma(qb.x, s2, tot2); tot3 = f2fma(qb.y, s3, tot3);
                }

                float tv[8];
                upk2(tot0, tv[0], tv[1]); upk2(tot1, tv[2], tv[3]);
                upk2(tot2, tv[4], tv[5]); upk2(tot3, tv[6], tv[7]);
                #pragma unroll
                for (int b = 0; b < 8; b++)
                    tv[b] += __shfl_xor_sync(0xFFFFFFFFu, tv[b], 1);

                // in-register RK state update + stage hsT for next eval
                #pragma unroll
                for (int bi_ = 0; bi_ < 4; bi_++) {
                    float kv = tv[fh * 4 + bi_];
                    float hs;
                    if (e == 0) {
                        k1r[bi_] = kv;
                        hs = fmaf(dti * (1.0f / 3.0f), k1r[bi_], hreg[bi_]);
                    } else if (e == 1) {
                        k2r[bi_] = kv;
                        hs = fmaf(dti, k2r[bi_] - k1r[bi_] * (1.0f / 3.0f), hreg[bi_]);
                    } else if (e == 2) {
                        k3r[bi_] = kv;
                        hs = fmaf(dti, k1r[bi_] - k2r[bi_] + k3r[bi_], hreg[bi_]);
                    } else {
                        hreg[bi_] = fmaf(dti * 0.125f,
                                         k1r[bi_] + 3.0f * (k2r[bi_] + k3r[bi_]) + kv,
                                         hreg[bi_]);
                        hs = hreg[bi_];
                    }
                    sh_hsT[j][fh * 4 + bi_] = hs;
                }
            }
            __syncthreads();
        }
    }

    // write final h from registers
    #pragma unroll
    for (int bi_ = 0; bi_ < 4; bi_++)
        out[(size_t)(gb0 + fh * 4 + bi_) * HD + j] = hreg[bi_];
}

extern "C" void kernel_launch(void* const* d_in, const int* in_sizes, int n_in,
                              void* d_out, int out_size) {
    const float* x   = (const float*)d_in[0];
    const float* W1  = (const float*)d_in[1];
    const float* b1  = (const float*)d_in[2];
    const float* W2  = (const float*)d_in[3];
    const float* b2  = (const float*)d_in[4];
    const float* Wi  = (const float*)d_in[5];
    const float* bi  = (const float*)d_in[6];
    float* out = (float*)d_out;
    perm_kernel<<<272, 256>>>(W1, W2);
    cde_kernel<<<NCTA, NT>>>(x, W1, b1, W2, b2, Wi, bi, out);
}